// round 1
// baseline (speedup 1.0000x reference)
#include <cuda_runtime.h>

#define N_ATOMS   100000
#define N_BONDS   200000
#define MAX_NB    6
#define ATOM_FDIM 133
#define BOND_FDIM 147
#define HIDDEN    256
#define N_MOLS    4096
#define MOL_FEAT  200
#define FFNN_HID  512
#define ENC_HID   256

// ---------------- scratch (device globals; no allocations allowed) ----------
__device__ float g_inputs[N_BONDS * HIDDEN];   // pre-relu W_i output
__device__ float g_msgA[N_BONDS * HIDDEN];
__device__ float g_msgB[N_BONDS * HIDDEN];
__device__ float g_amsg[N_ATOMS * HIDDEN];
__device__ float g_ah[N_ATOMS * HIDDEN];       // atom_hiddens
__device__ float g_sums[N_MOLS * HIDDEN];
__device__ float g_cnt[N_MOLS];
__device__ float g_molvec[N_MOLS * HIDDEN];
__device__ float g_hid[N_MOLS * FFNN_HID];

// ---------------- GEMM: out = relu(A @ W [+ addend] [+ bias]) ---------------
// AMODE 0: A = A0 [M,K]
// AMODE 1: A = concat(A0 [M,K0], A1 [M,K-K0]) along K
// AMODE 2: A[m,k] = A0[idxA[m]*K + k] - A1[idxR[m]*K + k]   (gather-diff)
#define BM 128
#define BN 128
#define BK 16

template<int AMODE, bool HAS_ADDEND, bool HAS_BIAS, bool WRITE_PRE>
__global__ void __launch_bounds__(256)
gemm_kernel(const float* __restrict__ A0, const float* __restrict__ A1, int K0,
            const int* __restrict__ idxA, const int* __restrict__ idxR,
            const float* __restrict__ W,
            const float* __restrict__ addend, const float* __restrict__ bias,
            float* __restrict__ outPre, float* __restrict__ out,
            int M, int K, int N)
{
    __shared__ float As[BK][BM + 1];
    __shared__ float Bs[BK][BN];
    __shared__ int   sIA[BM], sIR[BM];

    const int tid  = threadIdx.x;
    const int row0 = blockIdx.y * BM;
    const int col0 = blockIdx.x * BN;

    if (AMODE == 2) {
        if (tid < BM) {
            int r = row0 + tid;
            sIA[tid] = (r < M) ? idxA[r] : 0;
            sIR[tid] = (r < M) ? idxR[r] : 0;
        }
        __syncthreads();
    }

    const int a_k  = tid % BK;   // 0..15
    const int a_m0 = tid / BK;   // 0..15 (rows a_m0 + 16*r)
    const int b_n  = tid % BN;   // 0..127
    const int b_k0 = tid / BN;   // 0..1  (k = b_k0 + 2*r)
    const int tx   = tid % 16;
    const int ty   = tid / 16;

    float acc[8][8];
#pragma unroll
    for (int i = 0; i < 8; i++)
#pragma unroll
        for (int j = 0; j < 8; j++) acc[i][j] = 0.f;

    for (int k0g = 0; k0g < K; k0g += BK) {
        // ---- load A tile (As stored transposed: As[k][m]) ----
        const int kg = k0g + a_k;
#pragma unroll
        for (int r = 0; r < 8; r++) {
            const int m  = a_m0 + r * 16;
            const int mg = row0 + m;
            float v = 0.f;
            if (kg < K && mg < M) {
                if (AMODE == 0) {
                    v = A0[(long)mg * K + kg];
                } else if (AMODE == 1) {
                    v = (kg < K0) ? A0[(long)mg * K0 + kg]
                                  : A1[(long)mg * (K - K0) + (kg - K0)];
                } else {
                    v = A0[(long)sIA[m] * K + kg] - A1[(long)sIR[m] * K + kg];
                }
            }
            As[a_k][m] = v;
        }
        // ---- load B tile (W is [K,N] row-major, coalesced) ----
#pragma unroll
        for (int r = 0; r < 8; r++) {
            const int k   = b_k0 + r * 2;
            const int kg2 = k0g + k;
            Bs[k][b_n] = (kg2 < K) ? W[(long)kg2 * N + col0 + b_n] : 0.f;
        }
        __syncthreads();

#pragma unroll
        for (int k = 0; k < BK; k++) {
            float a[8], b[8];
#pragma unroll
            for (int i = 0; i < 8; i++) a[i] = As[k][ty + i * 16];
#pragma unroll
            for (int j = 0; j < 8; j++) b[j] = Bs[k][tx + j * 16];
#pragma unroll
            for (int i = 0; i < 8; i++)
#pragma unroll
                for (int j = 0; j < 8; j++)
                    acc[i][j] = fmaf(a[i], b[j], acc[i][j]);
        }
        __syncthreads();
    }

#pragma unroll
    for (int i = 0; i < 8; i++) {
        const int rg = row0 + ty + i * 16;
        if (rg >= M) continue;
#pragma unroll
        for (int j = 0; j < 8; j++) {
            const int cg = col0 + tx + j * 16;
            float v = acc[i][j];
            if (HAS_ADDEND) v += addend[(long)rg * N + cg];
            if (HAS_BIAS)   v += bias[cg];
            if (WRITE_PRE)  outPre[(long)rg * N + cg] = v;
            out[(long)rg * N + cg] = fmaxf(v, 0.f);
        }
    }
}

// ---------------- a_message[a] = sum_j message[a2b[a][j]] --------------------
__global__ void amsg_kernel(const float* __restrict__ msg,
                            const int* __restrict__ a2b,
                            float* __restrict__ amsg)
{
    const int t    = blockIdx.x * blockDim.x + threadIdx.x;
    const int atom = t >> 6;          // 64 threads per atom
    const int c4   = (t & 63) * 4;    // 4 floats each
    if (atom >= N_ATOMS) return;
    float4 s = make_float4(0.f, 0.f, 0.f, 0.f);
#pragma unroll
    for (int j = 0; j < MAX_NB; j++) {
        const int b = a2b[atom * MAX_NB + j];
        const float4 v = *(const float4*)(msg + (long)b * HIDDEN + c4);
        s.x += v.x; s.y += v.y; s.z += v.z; s.w += v.w;
    }
    *(float4*)(amsg + (long)atom * HIDDEN + c4) = s;
}

// ---------------- segment sum (atom2mol) -------------------------------------
__global__ void seg_kernel(const float* __restrict__ ah,
                           const int* __restrict__ a2m,
                           float* __restrict__ sums,
                           float* __restrict__ cnt)
{
    const int t    = blockIdx.x * blockDim.x + threadIdx.x;
    const int atom = t >> 8;
    const int c    = t & 255;
    if (atom >= N_ATOMS) return;
    const int m = a2m[atom];
    atomicAdd(&sums[(long)m * HIDDEN + c], ah[(long)atom * HIDDEN + c]);
    if (c == 0) atomicAdd(&cnt[m], 1.0f);
}

__global__ void divide_kernel(const float* __restrict__ sums,
                              const float* __restrict__ cnt,
                              float* __restrict__ molvec)
{
    const int t = blockIdx.x * blockDim.x + threadIdx.x;
    if (t >= N_MOLS * HIDDEN) return;
    const int m = t >> 8;
    molvec[t] = sums[t] / fmaxf(cnt[m], 1.0f);
}

// ---------------- launch -----------------------------------------------------
extern "C" void kernel_launch(void* const* d_in, const int* in_sizes, int n_in,
                              void* d_out, int out_size)
{
    const float* f_atoms      = (const float*)d_in[0];
    const float* f_bonds      = (const float*)d_in[1];
    const int*   a2b          = (const int*)  d_in[2];
    const int*   b2a          = (const int*)  d_in[3];
    const int*   b2revb       = (const int*)  d_in[4];
    const int*   atom2mol     = (const int*)  d_in[5];
    const float* mol_features = (const float*)d_in[6];
    const float* W_i          = (const float*)d_in[7];
    const float* W_h          = (const float*)d_in[8];
    const float* W_o_w        = (const float*)d_in[9];
    const float* W_o_b        = (const float*)d_in[10];
    const float* W1           = (const float*)d_in[11];
    const float* b1           = (const float*)d_in[12];
    const float* W2           = (const float*)d_in[13];
    const float* b2           = (const float*)d_in[14];
    float* out = (float*)d_out;

    float *inputs, *msgA, *msgB, *amsg, *ah, *sums, *cnt, *molvec, *hid;
    cudaGetSymbolAddress((void**)&inputs, g_inputs);
    cudaGetSymbolAddress((void**)&msgA,   g_msgA);
    cudaGetSymbolAddress((void**)&msgB,   g_msgB);
    cudaGetSymbolAddress((void**)&amsg,   g_amsg);
    cudaGetSymbolAddress((void**)&ah,     g_ah);
    cudaGetSymbolAddress((void**)&sums,   g_sums);
    cudaGetSymbolAddress((void**)&cnt,    g_cnt);
    cudaGetSymbolAddress((void**)&molvec, g_molvec);
    cudaGetSymbolAddress((void**)&hid,    g_hid);

    const dim3 gBond(HIDDEN / BN, (N_BONDS + BM - 1) / BM);  // (2, 1563)
    const dim3 gAtom(HIDDEN / BN, (N_ATOMS + BM - 1) / BM);  // (2, 782)
    const int  amsgBlocks = (N_ATOMS * 64 + 255) / 256;
    const int  segBlocks  = (N_ATOMS * 256) / 256;

    // 1) inputs = f_bonds @ W_i ; msgA = relu(inputs)
    gemm_kernel<0, false, false, true><<<gBond, 256>>>(
        f_bonds, nullptr, 0, nullptr, nullptr, W_i,
        nullptr, nullptr, inputs, msgA, N_BONDS, BOND_FDIM, HIDDEN);

    // 2) depth iteration 1: msgA -> msgB
    amsg_kernel<<<amsgBlocks, 256>>>(msgA, a2b, amsg);
    gemm_kernel<2, true, false, false><<<gBond, 256>>>(
        amsg, msgA, 0, b2a, b2revb, W_h,
        inputs, nullptr, nullptr, msgB, N_BONDS, HIDDEN, HIDDEN);

    // 3) depth iteration 2: msgB -> msgA
    amsg_kernel<<<amsgBlocks, 256>>>(msgB, a2b, amsg);
    gemm_kernel<2, true, false, false><<<gBond, 256>>>(
        amsg, msgB, 0, b2a, b2revb, W_h,
        inputs, nullptr, nullptr, msgA, N_BONDS, HIDDEN, HIDDEN);

    // 4) final neighbor aggregation
    amsg_kernel<<<amsgBlocks, 256>>>(msgA, a2b, amsg);

    // 5) atom_hiddens = relu([f_atoms | amsg] @ W_o_w + W_o_b)
    gemm_kernel<1, false, true, false><<<gAtom, 256>>>(
        f_atoms, amsg, ATOM_FDIM, nullptr, nullptr, W_o_w,
        nullptr, W_o_b, nullptr, ah, N_ATOMS, ATOM_FDIM + HIDDEN, HIDDEN);

    // 6) per-molecule mean pool
    cudaMemsetAsync(sums, 0, (size_t)N_MOLS * HIDDEN * sizeof(float));
    cudaMemsetAsync(cnt,  0, (size_t)N_MOLS * sizeof(float));
    seg_kernel<<<segBlocks, 256>>>(ah, atom2mol, sums, cnt);
    divide_kernel<<<(N_MOLS * HIDDEN + 255) / 256, 256>>>(sums, cnt, molvec);

    // 7) FFNN layer 1: hid = relu([molvec | mol_features] @ W1 + b1)
    gemm_kernel<1, false, true, false><<<dim3(FFNN_HID / BN, N_MOLS / BM), 256>>>(
        molvec, mol_features, HIDDEN, nullptr, nullptr, W1,
        nullptr, b1, nullptr, hid, N_MOLS, HIDDEN + MOL_FEAT, FFNN_HID);

    // 8) FFNN layer 2: out = relu(hid @ W2 + b2)
    gemm_kernel<0, false, true, false><<<dim3(ENC_HID / BN, N_MOLS / BM), 256>>>(
        hid, nullptr, 0, nullptr, nullptr, W2,
        nullptr, b2, nullptr, out, N_MOLS, FFNN_HID, ENC_HID);
}

// round 3
// speedup vs baseline: 1.6346x; 1.6346x over previous
#include <cuda_runtime.h>
#include <mma.h>
#include <cstdint>

using namespace nvcuda;

#define N_ATOMS   100000
#define N_BONDS   200000
#define MAX_NB    6
#define ATOM_FDIM 133
#define BOND_FDIM 147
#define HIDDEN    256
#define N_MOLS    4096
#define MOL_FEAT  200
#define FFNN_HID  512
#define ENC_HID   256

// ---------------- scratch (device globals; no allocations allowed) ----------
__device__ float g_inputs[N_BONDS * HIDDEN];
__device__ float g_msgA[N_BONDS * HIDDEN];
__device__ float g_msgB[N_BONDS * HIDDEN];
__device__ float g_amsg[N_ATOMS * HIDDEN];
__device__ float g_ah[N_ATOMS * HIDDEN];
__device__ float g_sums[N_MOLS * HIDDEN];
__device__ float g_cnt[N_MOLS];
__device__ float g_molvec[N_MOLS * HIDDEN];
__device__ float g_hid[N_MOLS * FFNN_HID];

// ---------------- wmma tf32 GEMM ---------------------------------------------
// out = relu(A @ W [+addend] [+bias]); W is [K,N] row-major (used directly as
// matrix_b row_major — no transpose needed).
// AMODE 0: A = A0 [M,K]
// AMODE 1: A = concat(A0 [M,K0], A1 [M,K-K0])
// AMODE 2: A[m,k] = A0[idxA[m]*K + k] - A1[idxR[m]*K + k]   (gather-diff)
// Tiles: BM=128, BN=128, BK=32. 8 warps, warp tile 32x64 (2x4 wmma frags).

#define AS_LD 36                 // A smem row stride (floats)
#define BS_LD 132                // B smem row stride (floats)
#define SMEM_FLOATS (128 * AS_LD + 32 * BS_LD)   // 8832 floats = 35328 B

template<int AMODE, bool VEC, bool HAS_ADDEND, bool HAS_BIAS, bool WRITE_PRE>
__global__ void __launch_bounds__(256)
gemm_wmma(const float* __restrict__ A0, const float* __restrict__ A1, int K0,
          const int* __restrict__ idxA, const int* __restrict__ idxR,
          const float* __restrict__ W,
          const float* __restrict__ addend, const float* __restrict__ bias,
          float* __restrict__ outPre, float* __restrict__ out,
          int M, int K, int N)
{
    extern __shared__ float smem[];
    float* As = smem;                    // [128][AS_LD]
    float* Bs = smem + 128 * AS_LD;      // [32][BS_LD]
    float* cbuf = smem;                  // reused after mainloop: 8 warps x 1024

    __shared__ int sIA[128], sIR[128];

    const int tid  = threadIdx.x;
    const int wid  = tid >> 5;
    const int lane = tid & 31;
    const int wm   = wid & 3;            // warp row  (4 x 32)
    const int wn   = wid >> 2;           // warp col  (2 x 64)
    const int row0 = blockIdx.y * 128;
    const int col0 = blockIdx.x * 128;

    if (AMODE == 2) {
        if (tid < 128) {
            const int r = row0 + tid;
            sIA[tid] = (r < M) ? idxA[r] : 0;
            sIR[tid] = (r < M) ? idxR[r] : 0;
        }
        __syncthreads();
    }

    wmma::fragment<wmma::accumulator, 16, 16, 8, float> acc[2][4];
#pragma unroll
    for (int i = 0; i < 2; i++)
#pragma unroll
        for (int j = 0; j < 4; j++) wmma::fill_fragment(acc[i][j], 0.0f);

    const int a_m  = tid >> 3;           // 0..31 (rows a_m + 32r)
    const int a_kq = tid & 7;            // float4 index within 32-float row
    const int b_k  = tid >> 5;           // 0..7  (rows b_k + 8r)
    const int b_n4 = tid & 31;           // float4 index within 128-float row

    const int KT = (K + 31) / 32;
    for (int t = 0; t < KT; t++) {
        const int k0g = t * 32;
        // ---- stage A tile [128][32] ----
#pragma unroll
        for (int r = 0; r < 4; r++) {
            const int m  = a_m + r * 32;
            const int mg = row0 + m;
            const int kg = k0g + a_kq * 4;
            float4 v = make_float4(0.f, 0.f, 0.f, 0.f);
            if (AMODE == 2) {
                const float4 x = *(const float4*)(A0 + (long)sIA[m] * K + kg);
                const float4 y = *(const float4*)(A1 + (long)sIR[m] * K + kg);
                v = make_float4(x.x - y.x, x.y - y.y, x.z - y.z, x.w - y.w);
            } else if (VEC) {
                if (mg < M && kg + 4 <= K) {
                    if (AMODE == 0) v = *(const float4*)(A0 + (long)mg * K + kg);
                    else v = (kg < K0) ? *(const float4*)(A0 + (long)mg * K0 + kg)
                                       : *(const float4*)(A1 + (long)mg * (K - K0) + (kg - K0));
                }
            } else {
                if (mg < M) {
                    float e[4];
#pragma unroll
                    for (int c = 0; c < 4; c++) {
                        const int k = kg + c;
                        float x = 0.f;
                        if (k < K) {
                            if (AMODE == 0) x = A0[(long)mg * K + k];
                            else x = (k < K0) ? A0[(long)mg * K0 + k]
                                              : A1[(long)mg * (K - K0) + (k - K0)];
                        }
                        e[c] = x;
                    }
                    v = make_float4(e[0], e[1], e[2], e[3]);
                }
            }
            *(float4*)(As + m * AS_LD + a_kq * 4) = v;
        }
        // ---- stage B tile [32][128] from W[K,N] ----
#pragma unroll
        for (int r = 0; r < 4; r++) {
            const int k   = b_k + r * 8;
            const int kg2 = k0g + k;
            float4 v = make_float4(0.f, 0.f, 0.f, 0.f);
            if (kg2 < K) v = *(const float4*)(W + (long)kg2 * N + col0 + b_n4 * 4);
            *(float4*)(Bs + k * BS_LD + b_n4 * 4) = v;
        }
        __syncthreads();

        // ---- mma: 4 k-steps of 8 ----
#pragma unroll
        for (int kk = 0; kk < 32; kk += 8) {
            wmma::fragment<wmma::matrix_a, 16, 16, 8, wmma::precision::tf32, wmma::row_major> af[2];
            wmma::fragment<wmma::matrix_b, 16, 16, 8, wmma::precision::tf32, wmma::row_major> bf[4];
#pragma unroll
            for (int i = 0; i < 2; i++) {
                wmma::load_matrix_sync(af[i], As + (wm * 32 + i * 16) * AS_LD + kk, AS_LD);
#pragma unroll
                for (int e = 0; e < af[i].num_elements; e++)
                    af[i].x[e] = wmma::__float_to_tf32(af[i].x[e]);
            }
#pragma unroll
            for (int j = 0; j < 4; j++) {
                wmma::load_matrix_sync(bf[j], Bs + kk * BS_LD + wn * 64 + j * 16, BS_LD);
#pragma unroll
                for (int e = 0; e < bf[j].num_elements; e++)
                    bf[j].x[e] = wmma::__float_to_tf32(bf[j].x[e]);
            }
#pragma unroll
            for (int i = 0; i < 2; i++)
#pragma unroll
                for (int j = 0; j < 4; j++)
                    wmma::mma_sync(acc[i][j], af[i], bf[j], acc[i][j]);
        }
        __syncthreads();
    }

    // ---- epilogue: stage 32x32 halves per warp through smem ----
    float* cw = cbuf + wid * 1024;       // 32 x 32 floats
#pragma unroll
    for (int h = 0; h < 2; h++) {
#pragma unroll
        for (int i = 0; i < 2; i++)
#pragma unroll
            for (int jj = 0; jj < 2; jj++)
                wmma::store_matrix_sync(cw + i * 16 * 32 + jj * 16,
                                        acc[i][h * 2 + jj], 32, wmma::mem_row_major);
        __syncwarp();
#pragma unroll
        for (int it = 0; it < 8; it++) {
            const int f4  = lane + it * 32;    // 0..255
            const int row = f4 >> 3;
            const int c4  = f4 & 7;
            const int rg  = row0 + wm * 32 + row;
            if (rg < M) {
                const int cg = col0 + wn * 64 + h * 32 + c4 * 4;
                float4 v = *(float4*)(cw + row * 32 + c4 * 4);
                const long base = (long)rg * N + cg;
                if (HAS_ADDEND) {
                    const float4 a = *(const float4*)(addend + base);
                    v.x += a.x; v.y += a.y; v.z += a.z; v.w += a.w;
                }
                if (HAS_BIAS) {
                    const float4 b = *(const float4*)(bias + cg);
                    v.x += b.x; v.y += b.y; v.z += b.z; v.w += b.w;
                }
                if (WRITE_PRE) *(float4*)(outPre + base) = v;
                *(float4*)(out + base) =
                    make_float4(fmaxf(v.x, 0.f), fmaxf(v.y, 0.f), fmaxf(v.z, 0.f), fmaxf(v.w, 0.f));
            }
        }
        __syncwarp();
    }
}

// ---------------- a_message[a] = sum_j message[a2b[a][j]] --------------------
__global__ void amsg_kernel(const float* __restrict__ msg,
                            const int* __restrict__ a2b,
                            float* __restrict__ amsg)
{
    const int t    = blockIdx.x * blockDim.x + threadIdx.x;
    const int atom = t >> 6;
    const int c4   = (t & 63) * 4;
    if (atom >= N_ATOMS) return;
    float4 s = make_float4(0.f, 0.f, 0.f, 0.f);
#pragma unroll
    for (int j = 0; j < MAX_NB; j++) {
        const int b = a2b[atom * MAX_NB + j];
        const float4 v = *(const float4*)(msg + (long)b * HIDDEN + c4);
        s.x += v.x; s.y += v.y; s.z += v.z; s.w += v.w;
    }
    *(float4*)(amsg + (long)atom * HIDDEN + c4) = s;
}

// ---------------- segment sum + mean ----------------------------------------
__global__ void seg_kernel(const float* __restrict__ ah,
                           const int* __restrict__ a2m,
                           float* __restrict__ sums,
                           float* __restrict__ cnt)
{
    const int t    = blockIdx.x * blockDim.x + threadIdx.x;
    const int atom = t >> 8;
    const int c    = t & 255;
    if (atom >= N_ATOMS) return;
    const int m = a2m[atom];
    atomicAdd(&sums[(long)m * HIDDEN + c], ah[(long)atom * HIDDEN + c]);
    if (c == 0) atomicAdd(&cnt[m], 1.0f);
}

__global__ void divide_kernel(const float* __restrict__ sums,
                              const float* __restrict__ cnt,
                              float* __restrict__ molvec)
{
    const int t = blockIdx.x * blockDim.x + threadIdx.x;
    if (t >= N_MOLS * HIDDEN) return;
    molvec[t] = sums[t] / fmaxf(cnt[t >> 8], 1.0f);
}

// ---------------- launch -----------------------------------------------------
extern "C" void kernel_launch(void* const* d_in, const int* in_sizes, int n_in,
                              void* d_out, int out_size)
{
    const float* f_atoms      = (const float*)d_in[0];
    const float* f_bonds      = (const float*)d_in[1];
    const int*   a2b          = (const int*)  d_in[2];
    const int*   b2a          = (const int*)  d_in[3];
    const int*   b2revb       = (const int*)  d_in[4];
    const int*   atom2mol     = (const int*)  d_in[5];
    const float* mol_features = (const float*)d_in[6];
    const float* W_i          = (const float*)d_in[7];
    const float* W_h          = (const float*)d_in[8];
    const float* W_o_w        = (const float*)d_in[9];
    const float* W_o_b        = (const float*)d_in[10];
    const float* W1           = (const float*)d_in[11];
    const float* b1           = (const float*)d_in[12];
    const float* W2           = (const float*)d_in[13];
    const float* b2           = (const float*)d_in[14];
    float* out = (float*)d_out;

    float *inputs, *msgA, *msgB, *amsg, *ah, *sums, *cnt, *molvec, *hid;
    cudaGetSymbolAddress((void**)&inputs, g_inputs);
    cudaGetSymbolAddress((void**)&msgA,   g_msgA);
    cudaGetSymbolAddress((void**)&msgB,   g_msgB);
    cudaGetSymbolAddress((void**)&amsg,   g_amsg);
    cudaGetSymbolAddress((void**)&ah,     g_ah);
    cudaGetSymbolAddress((void**)&sums,   g_sums);
    cudaGetSymbolAddress((void**)&cnt,    g_cnt);
    cudaGetSymbolAddress((void**)&molvec, g_molvec);
    cudaGetSymbolAddress((void**)&hid,    g_hid);

    const size_t smemBytes = SMEM_FLOATS * sizeof(float);   // 35328
    const dim3 gBond(HIDDEN / 128, (N_BONDS + 127) / 128);  // (2, 1563)
    const dim3 gAtom(HIDDEN / 128, (N_ATOMS + 127) / 128);  // (2, 782)
    const int  amsgBlocks = (N_ATOMS * 64 + 255) / 256;
    const int  segBlocks  = (N_ATOMS * 256) / 256;

    // 1) inputs = f_bonds @ W_i ; msgA = relu(inputs)
    gemm_wmma<0, false, false, false, true><<<gBond, 256, smemBytes>>>(
        f_bonds, nullptr, 0, nullptr, nullptr, W_i,
        nullptr, nullptr, inputs, msgA, N_BONDS, BOND_FDIM, HIDDEN);

    // 2) depth iter 1: msgA -> msgB
    amsg_kernel<<<amsgBlocks, 256>>>(msgA, a2b, amsg);
    gemm_wmma<2, true, true, false, false><<<gBond, 256, smemBytes>>>(
        amsg, msgA, 0, b2a, b2revb, W_h,
        inputs, nullptr, nullptr, msgB, N_BONDS, HIDDEN, HIDDEN);

    // 3) depth iter 2: msgB -> msgA
    amsg_kernel<<<amsgBlocks, 256>>>(msgB, a2b, amsg);
    gemm_wmma<2, true, true, false, false><<<gBond, 256, smemBytes>>>(
        amsg, msgB, 0, b2a, b2revb, W_h,
        inputs, nullptr, nullptr, msgA, N_BONDS, HIDDEN, HIDDEN);

    // 4) final aggregation
    amsg_kernel<<<amsgBlocks, 256>>>(msgA, a2b, amsg);

    // 5) atom_hiddens = relu([f_atoms | amsg] @ W_o_w + W_o_b)
    gemm_wmma<1, false, false, true, false><<<gAtom, 256, smemBytes>>>(
        f_atoms, amsg, ATOM_FDIM, nullptr, nullptr, W_o_w,
        nullptr, W_o_b, nullptr, ah, N_ATOMS, ATOM_FDIM + HIDDEN, HIDDEN);

    // 6) per-molecule mean pool
    cudaMemsetAsync(sums, 0, (size_t)N_MOLS * HIDDEN * sizeof(float));
    cudaMemsetAsync(cnt,  0, (size_t)N_MOLS * sizeof(float));
    seg_kernel<<<segBlocks, 256>>>(ah, atom2mol, sums, cnt);
    divide_kernel<<<(N_MOLS * HIDDEN + 255) / 256, 256>>>(sums, cnt, molvec);

    // 7) FFNN layer 1: hid = relu([molvec | mol_features] @ W1 + b1)
    gemm_wmma<1, true, false, true, false><<<dim3(FFNN_HID / 128, N_MOLS / 128), 256, smemBytes>>>(
        molvec, mol_features, HIDDEN, nullptr, nullptr, W1,
        nullptr, b1, nullptr, hid, N_MOLS, HIDDEN + MOL_FEAT, FFNN_HID);

    // 8) FFNN layer 2: out = relu(hid @ W2 + b2)
    gemm_wmma<0, true, false, true, false><<<dim3(ENC_HID / 128, N_MOLS / 128), 256, smemBytes>>>(
        hid, nullptr, 0, nullptr, nullptr, W2,
        nullptr, b2, nullptr, out, N_MOLS, FFNN_HID, ENC_HID);
}